// round 7
// baseline (speedup 1.0000x reference)
#include <cuda_runtime.h>
#include <math.h>

#define Bb 8
#define Nn 4096
#define Dd 128
#define Kk 256

// ---- output layout (flattened tuple, float32) ----
#define OFF_S    0
#define OFF_FC   32768
#define OFF_FCM  294912
#define OFF_FNCM 295936

// ---- scratch (device globals: allocation-free per harness rules) ----
__device__ float  g_A[134217728];          // 8*4096*4096 |corr| (512MB)
__device__ float  g_Xc[4194304];           // centered X
__device__ double g_meanpart[Bb][32][Dd];  // per-chunk column sums (double)
__device__ float  g_mean[Bb * Dd];         // per-feature mean
__device__ float  g_colsum[Bb * Dd];       // per-feature total sum
__device__ float  g_r[Bb * Nn];            // 1/var per row
__device__ float  g_y[Bb * Nn];            // X @ W^T
__device__ float  g_rowpart[Bb][64][Nn];   // rowsum partials [b][coltile][n]
__device__ float  g_dvec[Bb * Nn];         // rowsum^-0.5
__device__ float  g_w[Bb * Nn];            // d * y
__device__ int    g_idx[Bb * Kk];          // top-k indices

// ------------------------------------------------------------------
// column-sum partials: grid (32, B), 128 threads (thread = feature d)
__global__ void k_meanpart(const float* __restrict__ X) {
    int b = blockIdx.y, c = blockIdx.x, d = threadIdx.x;
    const float* p = X + ((size_t)b * Nn + (size_t)c * 128) * Dd + d;
    double s = 0.0;
#pragma unroll 4
    for (int n = 0; n < 128; ++n) s += (double)p[(size_t)n * Dd];
    g_meanpart[b][c][d] = s;
}

// deterministic reduce -> mean (float), colsum (float)
__global__ void k_meanred() {
    int i = blockIdx.x * 256 + threadIdx.x;   // 1024 = B*D
    if (i >= Bb * Dd) return;
    int b = i >> 7, d = i & 127;
    double s = 0.0;
    for (int c = 0; c < 32; ++c) s += g_meanpart[b][c][d];
    g_colsum[i] = (float)s;
    g_mean[i]   = (float)(s / (double)Nn);
}

// ------------------------------------------------------------------
// per-row: xc = x - mean, var = sqrtf(sum xc^2)+1e-6, r = 1/var, y = x.W
// grid B*N blocks, 128 threads (thread = feature d)
__global__ void k_vary(const float* __restrict__ X, const float* __restrict__ W) {
    int rowg = blockIdx.x;            // b*N + n
    int b = rowg >> 12;
    int d = threadIdx.x;

    float x  = X[(size_t)rowg * Dd + d];
    float m  = g_mean[b * Dd + d];
    float xc = x - m;
    double ss = (double)xc * (double)xc;
    double yv = (double)x * (double)W[d];

    for (int o = 16; o; o >>= 1) {
        ss += __shfl_down_sync(0xFFFFFFFFu, ss, o);
        yv += __shfl_down_sync(0xFFFFFFFFu, yv, o);
    }
    __shared__ double sss[4], syv[4];
    int wid = threadIdx.x >> 5, lane = threadIdx.x & 31;
    if (lane == 0) { sss[wid] = ss; syv[wid] = yv; }
    __syncthreads();

    g_Xc[(size_t)rowg * Dd + d] = xc;
    if (d == 0) {
        float ssT = (float)(sss[0] + sss[1] + sss[2] + sss[3]);
        float var = sqrtf(ssT) + 1e-6f;
        g_r[rowg] = 1.0f / var;                 // IEEE division
        g_y[rowg] = (float)(syv[0] + syv[1] + syv[2] + syv[3]);
    }
}

// ------------------------------------------------------------------
// Phase 1: cov = Xc Xc^T per batch, upper-triangle 64x64 tiles,
// A = |cov * r_i * r_j|; write tile + transpose; deterministic row/col
// partial sums (Kahan). grid (2080, B), 256 threads, 66560B dyn smem.
__global__ void __launch_bounds__(256) k_corr() {
    extern __shared__ float smem[];
    float* sa = smem;            // [128][65] transposed
    float* sb = smem + 8320;     // [128][65]
    float* sc = smem;            // overlay after compute: [64][65]
    __shared__ float rrow[64], rcol[64];

    int b = blockIdx.y;
    int p = blockIdx.x;
    int ti = 0;
    while (p >= 64 - ti) { p -= 64 - ti; ++ti; }
    int tj = ti + p;
    int bRow = ti * 64, bCol = tj * 64;

    const float* Xb = g_Xc + (size_t)b * Nn * Dd;
    int t = threadIdx.x;

    if (t < 64)            rrow[t]      = g_r[b * Nn + bRow + t];
    else if (t < 128)      rcol[t - 64] = g_r[b * Nn + bCol + (t - 64)];

#pragma unroll
    for (int i = 0; i < 8; ++i) {
        int idx = t + 256 * i;
        int row = idx >> 5;
        int kq  = (idx & 31) << 2;
        float4 va = *(const float4*)(Xb + (size_t)(bRow + row) * Dd + kq);
        sa[(kq + 0) * 65 + row] = va.x;
        sa[(kq + 1) * 65 + row] = va.y;
        sa[(kq + 2) * 65 + row] = va.z;
        sa[(kq + 3) * 65 + row] = va.w;
        float4 vb = *(const float4*)(Xb + (size_t)(bCol + row) * Dd + kq);
        sb[(kq + 0) * 65 + row] = vb.x;
        sb[(kq + 1) * 65 + row] = vb.y;
        sb[(kq + 2) * 65 + row] = vb.z;
        sb[(kq + 3) * 65 + row] = vb.w;
    }
    __syncthreads();

    int tx = t & 15, ty = t >> 4;
    int r0 = ty * 4, c0 = tx * 4;
    float acc[4][4];
#pragma unroll
    for (int i = 0; i < 4; ++i)
#pragma unroll
        for (int j = 0; j < 4; ++j) acc[i][j] = 0.f;

#pragma unroll 8
    for (int k = 0; k < 128; ++k) {   // sequential K: BLAS-like accumulation order
        float a0 = sa[k * 65 + r0 + 0];
        float a1 = sa[k * 65 + r0 + 1];
        float a2 = sa[k * 65 + r0 + 2];
        float a3 = sa[k * 65 + r0 + 3];
        float b0 = sb[k * 65 + c0 + 0];
        float b1 = sb[k * 65 + c0 + 1];
        float b2 = sb[k * 65 + c0 + 2];
        float b3 = sb[k * 65 + c0 + 3];
        acc[0][0] += a0 * b0; acc[0][1] += a0 * b1; acc[0][2] += a0 * b2; acc[0][3] += a0 * b3;
        acc[1][0] += a1 * b0; acc[1][1] += a1 * b1; acc[1][2] += a1 * b2; acc[1][3] += a1 * b3;
        acc[2][0] += a2 * b0; acc[2][1] += a2 * b1; acc[2][2] += a2 * b2; acc[2][3] += a2 * b3;
        acc[3][0] += a3 * b0; acc[3][1] += a3 * b1; acc[3][2] += a3 * b2; acc[3][3] += a3 * b3;
    }
    __syncthreads();  // sa dead; sc overlays it

    // epilogue scale + abs, staged to shared [64][65]
#pragma unroll
    for (int i = 0; i < 4; ++i)
#pragma unroll
        for (int j = 0; j < 4; ++j)
            sc[(r0 + i) * 65 + (c0 + j)] =
                fabsf(acc[i][j] * rrow[r0 + i] * rcol[c0 + j]);
    __syncthreads();

    float* Ab = g_A + (size_t)b * Nn * Nn;

#pragma unroll
    for (int l = t; l < 4096; l += 256) {
        int n = l >> 6, m = l & 63;
        Ab[(size_t)(bRow + n) * Nn + (bCol + m)] = sc[n * 65 + m];
    }
    if (ti != tj) {
#pragma unroll
        for (int l = t; l < 4096; l += 256) {
            int mm = l >> 6, n = l & 63;
            Ab[(size_t)(bCol + mm) * Nn + (bRow + n)] = sc[n * 65 + mm];
        }
    }

    // deterministic partial sums (Kahan): each (n, tile) slot written once
    if (t < 64) {
        float s = 0.f, c = 0.f;
#pragma unroll 8
        for (int m = 0; m < 64; ++m) {
            float yk = sc[t * 65 + m] - c;
            float tt = s + yk;
            c = (tt - s) - yk;
            s = tt;
        }
        g_rowpart[b][tj][bRow + t] = s;
    } else if (t < 128 && ti != tj) {
        int mm = t - 64;
        float s = 0.f, c = 0.f;
#pragma unroll 8
        for (int n = 0; n < 64; ++n) {
            float yk = sc[n * 65 + mm] - c;
            float tt = s + yk;
            c = (tt - s) - yk;
            s = tt;
        }
        g_rowpart[b][ti][bCol + mm] = s;
    }
}

// ------------------------------------------------------------------
// rowsum reduce (Kahan, deterministic) ; d = rowsum^-0.5 ; w = d*y
__global__ void k_rowred() {
    int i = blockIdx.x * 256 + threadIdx.x;   // B*N = 32768
    int b = i >> 12, n = i & 4095;
    float s = 0.f, c = 0.f;
#pragma unroll 8
    for (int j = 0; j < 64; ++j) {
        float yk = g_rowpart[b][j][n] - c;
        float tt = s + yk;
        c = (tt - s) - yk;
        s = tt;
    }
    float dv = 1.0f / sqrtf(s);
    g_dvec[i] = dv;
    g_w[i] = dv * g_y[i];
}

// ------------------------------------------------------------------
// Phase 2: S[b,n] = d_n * sum_m A[n,m] * w[m]  (Kahan per-thread)
// grid (N, B), 128 threads
__global__ void k_gcn(float* __restrict__ Sout) {
    int b = blockIdx.y, n = blockIdx.x, t = threadIdx.x;
    const float* row = g_A + ((size_t)b * Nn + n) * Nn;
    const float* wb  = g_w + b * Nn;
    float s = 0.f, c = 0.f;
#pragma unroll
    for (int i = 0; i < 8; ++i) {
        int m = (t + i * 128) << 2;
        float4 a  = *(const float4*)(row + m);
        float4 ww = *(const float4*)(wb + m);
        float pr[4] = { a.x * ww.x, a.y * ww.y, a.z * ww.z, a.w * ww.w };
#pragma unroll
        for (int q = 0; q < 4; ++q) {
            float yk = pr[q] - c;
            float tt = s + yk;
            c = (tt - s) - yk;
            s = tt;
        }
    }
    float v = s + c;
    for (int o = 16; o; o >>= 1) v += __shfl_down_sync(0xFFFFFFFFu, v, o);
    __shared__ float sh[4];
    if ((t & 31) == 0) sh[t >> 5] = v;
    __syncthreads();
    if (t == 0)
        Sout[OFF_S + b * Nn + n] = g_dvec[b * Nn + n] * (sh[0] + sh[1] + sh[2] + sh[3]);
}

// ------------------------------------------------------------------
// top-K via bitonic sort of 4096 packed keys: descending score,
// ascending index on ties (matches lax.top_k).
__global__ void k_topk(const float* __restrict__ S) {
    __shared__ unsigned long long key[4096];
    int b = blockIdx.x;
    for (int i = threadIdx.x; i < 4096; i += 1024) {
        unsigned u  = __float_as_uint(S[OFF_S + b * Nn + i]);
        unsigned up = (u & 0x80000000u) ? ~u : (u | 0x80000000u);
        unsigned kd = ~up;
        key[i] = ((unsigned long long)kd << 32) | (unsigned)i;
    }
    __syncthreads();
    for (int size = 2; size <= 4096; size <<= 1) {
        for (int stride = size >> 1; stride; stride >>= 1) {
#pragma unroll
            for (int q = 0; q < 2; ++q) {
                int t  = threadIdx.x + q * 1024;
                int lo = 2 * t - (t & (stride - 1));
                int hi = lo + stride;
                bool asc = (lo & size) == 0;
                unsigned long long a = key[lo], c = key[hi];
                if ((a > c) == asc) { key[lo] = c; key[hi] = a; }
            }
            __syncthreads();
        }
    }
    if (threadIdx.x < Kk)
        g_idx[b * Kk + threadIdx.x] = (int)(key[threadIdx.x] & 0xFFFFFFFFu);
}

// ------------------------------------------------------------------
// gather F_c (top-k order) + both means. grid B, 128 threads (= d)
__global__ void k_gather(const float* __restrict__ X, float* __restrict__ out) {
    int b = blockIdx.x, d = threadIdx.x;
    float* Fc = out + OFF_FC + (size_t)b * Kk * Dd;
    float s = 0.f;
#pragma unroll 4
    for (int k = 0; k < Kk; ++k) {
        int n = g_idx[b * Kk + k];
        float v = X[((size_t)b * Nn + n) * Dd + d];
        Fc[k * Dd + d] = v;
        s += v;
    }
    out[OFF_FCM  + b * Dd + d] = s * (1.f / (float)Kk);
    out[OFF_FNCM + b * Dd + d] = (g_colsum[b * Dd + d] - s) * (1.f / (float)(Nn - Kk));
}

// ------------------------------------------------------------------
extern "C" void kernel_launch(void* const* d_in, const int* in_sizes, int n_in,
                              void* d_out, int out_size) {
    const float* X = (const float*)d_in[0];   // [8,4096,128] f32
    const float* W = (const float*)d_in[1];   // [1,128] f32
    float* out = (float*)d_out;

    dim3 gmp(32, Bb);
    k_meanpart<<<gmp, 128>>>(X);
    k_meanred<<<4, 256>>>();

    k_vary<<<Bb * Nn, 128>>>(X, W);

    cudaFuncSetAttribute((const void*)k_corr,
                         cudaFuncAttributeMaxDynamicSharedMemorySize, 66560);
    dim3 gc(2080, Bb);
    k_corr<<<gc, 256, 66560>>>();

    k_rowred<<<128, 256>>>();

    dim3 gg(Nn, Bb);
    k_gcn<<<gg, 128>>>(out);

    k_topk<<<Bb, 1024>>>(out);

    k_gather<<<Bb, 128>>>(X, out);
}

// round 8
// speedup vs baseline: 2.2148x; 2.2148x over previous
#include <cuda_runtime.h>
#include <math.h>

#define Bb 8
#define Nn 4096
#define Dd 128
#define Kk 256
#define NT 32            // N / 128 tile blocks
#define NTILES 528       // NT*(NT+1)/2 upper-triangle 128x128 tiles

// ---- output layout (flattened tuple, float32) ----
#define OFF_S    0
#define OFF_FC   32768
#define OFF_FCM  294912
#define OFF_FNCM 295936

// ---- scratch (device globals: allocation-free per harness rules) ----
__device__ float  g_A[134217728];          // 8*4096*4096; only upper tiles used
__device__ float  g_Xc[4194304];           // centered X
__device__ double g_meanpart[Bb][32][Dd];  // per-chunk column sums (double)
__device__ float  g_mean[Bb * Dd];
__device__ float  g_colsum[Bb * Dd];
__device__ float  g_r[Bb * Nn];            // 1/var per row
__device__ float  g_y[Bb * Nn];            // X @ W^T
__device__ float  g_rowpart[Bb][NT][Nn];   // rowsum partials (unique slots)
__device__ float  g_ypart[Bb][NT][Nn];     // matvec partials (unique slots)
__device__ float  g_dvec[Bb * Nn];         // rowsum^-0.5
__device__ float  g_w[Bb * Nn];            // d * y
__device__ int    g_idx[Bb * Kk];          // top-k indices

// ------------------------------------------------------------------
__global__ void k_meanpart(const float* __restrict__ X) {
    int b = blockIdx.y, c = blockIdx.x, d = threadIdx.x;
    const float* p = X + ((size_t)b * Nn + (size_t)c * 128) * Dd + d;
    double s = 0.0;
#pragma unroll 4
    for (int n = 0; n < 128; ++n) s += (double)p[(size_t)n * Dd];
    g_meanpart[b][c][d] = s;
}

__global__ void k_meanred() {
    int i = blockIdx.x * 256 + threadIdx.x;   // 1024 = B*D
    if (i >= Bb * Dd) return;
    int b = i >> 7, d = i & 127;
    double s = 0.0;
    for (int c = 0; c < 32; ++c) s += g_meanpart[b][c][d];
    g_colsum[i] = (float)s;
    g_mean[i]   = (float)(s / (double)Nn);
}

// ------------------------------------------------------------------
// per-row: xc, r = 1/(sqrtf(sum xc^2)+1e-6), y = x.W
__global__ void k_vary(const float* __restrict__ X, const float* __restrict__ W) {
    int rowg = blockIdx.x;            // b*N + n
    int b = rowg >> 12;
    int d = threadIdx.x;

    float x  = X[(size_t)rowg * Dd + d];
    float m  = g_mean[b * Dd + d];
    float xc = x - m;
    double ss = (double)xc * (double)xc;
    double yv = (double)x * (double)W[d];

    for (int o = 16; o; o >>= 1) {
        ss += __shfl_down_sync(0xFFFFFFFFu, ss, o);
        yv += __shfl_down_sync(0xFFFFFFFFu, yv, o);
    }
    __shared__ double sss[4], syv[4];
    int wid = threadIdx.x >> 5, lane = threadIdx.x & 31;
    if (lane == 0) { sss[wid] = ss; syv[wid] = yv; }
    __syncthreads();

    g_Xc[(size_t)rowg * Dd + d] = xc;
    if (d == 0) {
        float ssT = (float)(sss[0] + sss[1] + sss[2] + sss[3]);
        float var = sqrtf(ssT) + 1e-6f;
        g_r[rowg] = 1.0f / var;
        g_y[rowg] = (float)(syv[0] + syv[1] + syv[2] + syv[3]);
    }
}

// ------------------------------------------------------------------
__device__ __forceinline__ void tile_map(int p, int& ti, int& tj) {
    ti = 0;
    while (p >= NT - ti) { p -= NT - ti; ++ti; }
    tj = ti + p;
}

// ------------------------------------------------------------------
// Phase 1: 128x128 upper tiles of A = |cov * r_i * r_j|.
// 256 threads, 8x8 register tile per thread, BK=16.
// Writes only the straight tile + deterministic row/col partial sums.
__global__ void __launch_bounds__(256, 2) k_corr() {
    __shared__ float sa[16][128];
    __shared__ float sb[16][128];
    __shared__ float rrow[128], rcol[128];
    __shared__ float rs[128];

    int b = blockIdx.y;
    int ti, tj;
    tile_map(blockIdx.x, ti, tj);
    int bRow = ti * 128, bCol = tj * 128;

    const float* Xb = g_Xc + (size_t)b * Nn * Dd;
    int t = threadIdx.x;
    int tx = t & 15, ty = t >> 4;

    if (t < 128) rrow[t] = g_r[b * Nn + bRow + t];
    else         rcol[t - 128] = g_r[b * Nn + bCol + (t - 128)];

    float acc[8][8];
#pragma unroll
    for (int i = 0; i < 8; ++i)
#pragma unroll
        for (int j = 0; j < 8; ++j) acc[i][j] = 0.f;

    int mload = t >> 2;
    int kq = (t & 3) << 2;

    for (int kc = 0; kc < 128; kc += 16) {
#pragma unroll
        for (int pp = 0; pp < 2; ++pp) {
            int m = mload + pp * 64;
            float4 va = *(const float4*)(Xb + (size_t)(bRow + m) * Dd + kc + kq);
            sa[kq + 0][m] = va.x; sa[kq + 1][m] = va.y;
            sa[kq + 2][m] = va.z; sa[kq + 3][m] = va.w;
            float4 vb = *(const float4*)(Xb + (size_t)(bCol + m) * Dd + kc + kq);
            sb[kq + 0][m] = vb.x; sb[kq + 1][m] = vb.y;
            sb[kq + 2][m] = vb.z; sb[kq + 3][m] = vb.w;
        }
        __syncthreads();
#pragma unroll
        for (int k = 0; k < 16; ++k) {
            float af[8], bf[8];
            *(float4*)&af[0] = *(const float4*)&sa[k][ty * 4];
            *(float4*)&af[4] = *(const float4*)&sa[k][64 + ty * 4];
            *(float4*)&bf[0] = *(const float4*)&sb[k][tx * 4];
            *(float4*)&bf[4] = *(const float4*)&sb[k][64 + tx * 4];
#pragma unroll
            for (int i = 0; i < 8; ++i)
#pragma unroll
                for (int j = 0; j < 8; ++j)
                    acc[i][j] += af[i] * bf[j];
        }
        __syncthreads();
    }

    // epilogue: scale + abs in place
    float rr_[8], rc_[8];
#pragma unroll
    for (int i = 0; i < 8; ++i) {
        int r = (i < 4) ? (ty * 4 + i) : (64 + ty * 4 + i - 4);
        rr_[i] = rrow[r];
    }
#pragma unroll
    for (int j = 0; j < 8; ++j) {
        int c = (j < 4) ? (tx * 4 + j) : (64 + tx * 4 + j - 4);
        rc_[j] = rcol[c];
    }
#pragma unroll
    for (int i = 0; i < 8; ++i)
#pragma unroll
        for (int j = 0; j < 8; ++j)
            acc[i][j] = fabsf(acc[i][j] * rr_[i] * rc_[j]);

    // straight tile write (float4, coalesced)
    float* Ab = g_A + (size_t)b * Nn * Nn;
#pragma unroll
    for (int i = 0; i < 8; ++i) {
        int r = (i < 4) ? (ty * 4 + i) : (64 + ty * 4 + i - 4);
        float4 w0 = make_float4(acc[i][0], acc[i][1], acc[i][2], acc[i][3]);
        float4 w1 = make_float4(acc[i][4], acc[i][5], acc[i][6], acc[i][7]);
        *(float4*)(Ab + (size_t)(bRow + r) * Nn + bCol + tx * 4)      = w0;
        *(float4*)(Ab + (size_t)(bRow + r) * Nn + bCol + 64 + tx * 4) = w1;
    }

    // row sums: per-thread sum of 8 cols, xor-shuffle over the 16 tx lanes
#pragma unroll
    for (int i = 0; i < 8; ++i) {
        float lr = 0.f;
#pragma unroll
        for (int j = 0; j < 8; ++j) lr += acc[i][j];
        for (int o = 8; o; o >>= 1) lr += __shfl_xor_sync(0xFFFFFFFFu, lr, o, 16);
        if (tx == 0) {
            int r = (i < 4) ? (ty * 4 + i) : (64 + ty * 4 + i - 4);
            rs[r] = lr;
        }
    }

    // col partial sums: reuse sa as [16][128] scratch (dead after mainloop)
#pragma unroll
    for (int j = 0; j < 8; ++j) {
        float lc = 0.f;
#pragma unroll
        for (int i = 0; i < 8; ++i) lc += acc[i][j];
        int c = (j < 4) ? (tx * 4 + j) : (64 + tx * 4 + j - 4);
        sa[ty][c] = lc;
    }
    __syncthreads();

    if (t < 128) {
        g_rowpart[b][tj][bRow + t] = rs[t];
        if (ti != tj) {
            float s = 0.f;
#pragma unroll
            for (int q = 0; q < 16; ++q) s += sa[q][t];
            g_rowpart[b][ti][bCol + t] = s;
        }
    }
}

// ------------------------------------------------------------------
// rowsum reduce (Kahan) ; d = rowsum^-0.5 ; w = d*y
__global__ void k_rowred() {
    int i = blockIdx.x * 256 + threadIdx.x;   // B*N = 32768
    int b = i >> 12, n = i & 4095;
    float s = 0.f, c = 0.f;
#pragma unroll
    for (int j = 0; j < NT; ++j) {
        float yk = g_rowpart[b][j][n] - c;
        float tt = s + yk;
        c = (tt - s) - yk;
        s = tt;
    }
    float dv = 1.0f / sqrtf(s);
    g_dvec[i] = dv;
    g_w[i] = dv * g_y[i];
}

// ------------------------------------------------------------------
// Phase 2: symmetric tile matvec. Each upper tile T(ti,tj) contributes
//   u[r] = T[r][:] . w[bCol..]  -> ypart[b][tj][bRow+r]
//   v[c] = T[:][c] . w[bRow..]  -> ypart[b][ti][bCol+c]   (ti != tj)
// grid (528, B), 256 threads. DRAM-streaming 270MB.
__global__ void __launch_bounds__(256) k_spmv() {
    __shared__ float sm[32][128];
    __shared__ float wr[128], wc[128];
    __shared__ float usum[128], vsum[128];

    int b = blockIdx.y;
    int ti, tj;
    tile_map(blockIdx.x, ti, tj);
    int bRow = ti * 128, bCol = tj * 128;
    int t = threadIdx.x;

    if (t < 128) { wr[t] = g_w[b * Nn + bRow + t]; vsum[t] = 0.f; }
    else         { wc[t - 128] = g_w[b * Nn + bCol + (t - 128)]; }
    __syncthreads();

    const float* Ab = g_A + (size_t)b * Nn * Nn;

    for (int s = 0; s < 4; ++s) {
#pragma unroll
        for (int q = 0; q < 4; ++q) {
            int off = q * 1024 + t * 4;
            int row = off >> 7, col = off & 127;
            *(float4*)&sm[row][col] =
                *(const float4*)(Ab + (size_t)(bRow + s * 32 + row) * Nn + bCol + col);
        }
        __syncthreads();
        // u: 8 lanes per row, 16 elements each, xor-shuffle width 8
        {
            int rr = t >> 3, g = t & 7;
            float pu = 0.f;
#pragma unroll
            for (int q = 0; q < 16; ++q) pu += sm[rr][g * 16 + q] * wc[g * 16 + q];
            for (int o = 4; o; o >>= 1) pu += __shfl_xor_sync(0xFFFFFFFFu, pu, o, 8);
            if (g == 0) usum[s * 32 + rr] = pu;
        }
        // v: one thread per column, serial over 32 strip rows (deterministic)
        if (t < 128) {
            float pv = 0.f;
#pragma unroll
            for (int rr = 0; rr < 32; ++rr) pv += sm[rr][t] * wr[s * 32 + rr];
            vsum[t] += pv;
        }
        __syncthreads();
    }

    if (t < 128) {
        g_ypart[b][tj][bRow + t] = usum[t];
        if (ti != tj) g_ypart[b][ti][bCol + t] = vsum[t];
    }
}

// ------------------------------------------------------------------
// S = d * (sum of 32 matvec partials)  (Kahan)
__global__ void k_sred(float* __restrict__ out) {
    int i = blockIdx.x * 256 + threadIdx.x;   // 32768
    int b = i >> 12, n = i & 4095;
    float s = 0.f, c = 0.f;
#pragma unroll
    for (int j = 0; j < NT; ++j) {
        float yk = g_ypart[b][j][n] - c;
        float tt = s + yk;
        c = (tt - s) - yk;
        s = tt;
    }
    out[OFF_S + i] = g_dvec[i] * (s + c);
}

// ------------------------------------------------------------------
// top-K via bitonic sort: descending score, ascending index on ties.
__global__ void k_topk(const float* __restrict__ S) {
    __shared__ unsigned long long key[4096];
    int b = blockIdx.x;
    for (int i = threadIdx.x; i < 4096; i += 1024) {
        unsigned u  = __float_as_uint(S[OFF_S + b * Nn + i]);
        unsigned up = (u & 0x80000000u) ? ~u : (u | 0x80000000u);
        unsigned kd = ~up;
        key[i] = ((unsigned long long)kd << 32) | (unsigned)i;
    }
    __syncthreads();
    for (int size = 2; size <= 4096; size <<= 1) {
        for (int stride = size >> 1; stride; stride >>= 1) {
#pragma unroll
            for (int q = 0; q < 2; ++q) {
                int t  = threadIdx.x + q * 1024;
                int lo = 2 * t - (t & (stride - 1));
                int hi = lo + stride;
                bool asc = (lo & size) == 0;
                unsigned long long a = key[lo], c = key[hi];
                if ((a > c) == asc) { key[lo] = c; key[hi] = a; }
            }
            __syncthreads();
        }
    }
    if (threadIdx.x < Kk)
        g_idx[b * Kk + threadIdx.x] = (int)(key[threadIdx.x] & 0xFFFFFFFFu);
}

// ------------------------------------------------------------------
// gather F_c, parallel over (b, k-chunk). grid (16, 8), 128 threads.
__global__ void k_gather(const float* __restrict__ X, float* __restrict__ out) {
    int b = blockIdx.y, kc = blockIdx.x, d = threadIdx.x;
#pragma unroll
    for (int q = 0; q < 16; ++q) {
        int k = kc * 16 + q;
        int n = g_idx[b * Kk + k];
        out[OFF_FC + ((size_t)b * Kk + k) * Dd + d] = X[((size_t)b * Nn + n) * Dd + d];
    }
}

// means: grid B, 128 threads (= d); reads gathered F_c back from out
__global__ void k_means(const float* __restrict__ X, float* __restrict__ out) {
    int b = blockIdx.x, d = threadIdx.x;
    float s = 0.f;
#pragma unroll 4
    for (int k = 0; k < Kk; ++k) {
        int n = g_idx[b * Kk + k];
        s += X[((size_t)b * Nn + n) * Dd + d];
    }
    out[OFF_FCM  + b * Dd + d] = s * (1.f / (float)Kk);
    out[OFF_FNCM + b * Dd + d] = (g_colsum[b * Dd + d] - s) * (1.f / (float)(Nn - Kk));
}

// ------------------------------------------------------------------
extern "C" void kernel_launch(void* const* d_in, const int* in_sizes, int n_in,
                              void* d_out, int out_size) {
    const float* X = (const float*)d_in[0];   // [8,4096,128] f32
    const float* W = (const float*)d_in[1];   // [1,128] f32
    float* out = (float*)d_out;

    dim3 gmp(32, Bb);
    k_meanpart<<<gmp, 128>>>(X);
    k_meanred<<<4, 256>>>();

    k_vary<<<Bb * Nn, 128>>>(X, W);

    dim3 gc(NTILES, Bb);
    k_corr<<<gc, 256>>>();

    k_rowred<<<128, 256>>>();

    k_spmv<<<gc, 256>>>();

    k_sred<<<128, 256>>>(out);

    k_topk<<<Bb, 1024>>>(out);

    dim3 gg(16, Bb);
    k_gather<<<gg, 128>>>(X, out);
    k_means<<<Bb, 128>>>(X, out);
}

// round 9
// speedup vs baseline: 2.2168x; 1.0009x over previous
#include <cuda_runtime.h>
#include <math.h>

#define Bb 8
#define Nn 4096
#define Dd 128
#define Kk 256
#define NT 32            // N / 128 tile blocks
#define NTILES 528       // NT*(NT+1)/2 upper-triangle 128x128 tiles

// ---- output layout (flattened tuple, float32) ----
#define OFF_S    0
#define OFF_FC   32768
#define OFF_FCM  294912
#define OFF_FNCM 295936

// ---- scratch (device globals: allocation-free per harness rules) ----
__device__ float  g_A[134217728];          // 8*4096*4096; only upper tiles used
__device__ float  g_Xc[4194304];           // centered X
__device__ double g_meanpart[Bb][32][Dd];  // per-chunk column sums (double)
__device__ float  g_mean[Bb * Dd];
__device__ float  g_colsum[Bb * Dd];
__device__ float  g_r[Bb * Nn];            // 1/var per row
__device__ float  g_y[Bb * Nn];            // X @ W^T
__device__ float  g_rowpart[Bb][NT][Nn];   // rowsum partials (unique slots)
__device__ float  g_ypart[Bb][NT][Nn];     // matvec partials (unique slots)
__device__ float  g_dvec[Bb * Nn];         // rowsum^-0.5
__device__ float  g_w[Bb * Nn];            // d * y
__device__ int    g_idx[Bb * Kk];          // top-k indices

// ------------------------------------------------------------------
__global__ void k_meanpart(const float* __restrict__ X) {
    int b = blockIdx.y, c = blockIdx.x, d = threadIdx.x;
    const float* p = X + ((size_t)b * Nn + (size_t)c * 128) * Dd + d;
    double s = 0.0;
#pragma unroll 4
    for (int n = 0; n < 128; ++n) s += (double)p[(size_t)n * Dd];
    g_meanpart[b][c][d] = s;
}

__global__ void k_meanred() {
    int i = blockIdx.x * 256 + threadIdx.x;   // 1024 = B*D
    if (i >= Bb * Dd) return;
    int b = i >> 7, d = i & 127;
    double s = 0.0;
    for (int c = 0; c < 32; ++c) s += g_meanpart[b][c][d];
    g_colsum[i] = (float)s;
    g_mean[i]   = (float)(s / (double)Nn);
}

// ------------------------------------------------------------------
// per-row: xc, r = 1/(sqrtf(sum xc^2)+1e-6), y = x.W
__global__ void k_vary(const float* __restrict__ X, const float* __restrict__ W) {
    int rowg = blockIdx.x;            // b*N + n
    int b = rowg >> 12;
    int d = threadIdx.x;

    float x  = X[(size_t)rowg * Dd + d];
    float m  = g_mean[b * Dd + d];
    float xc = x - m;
    double ss = (double)xc * (double)xc;
    double yv = (double)x * (double)W[d];

    for (int o = 16; o; o >>= 1) {
        ss += __shfl_down_sync(0xFFFFFFFFu, ss, o);
        yv += __shfl_down_sync(0xFFFFFFFFu, yv, o);
    }
    __shared__ double sss[4], syv[4];
    int wid = threadIdx.x >> 5, lane = threadIdx.x & 31;
    if (lane == 0) { sss[wid] = ss; syv[wid] = yv; }
    __syncthreads();

    g_Xc[(size_t)rowg * Dd + d] = xc;
    if (d == 0) {
        float ssT = (float)(sss[0] + sss[1] + sss[2] + sss[3]);
        float var = sqrtf(ssT) + 1e-6f;
        g_r[rowg] = 1.0f / var;
        g_y[rowg] = (float)(syv[0] + syv[1] + syv[2] + syv[3]);
    }
}

// ------------------------------------------------------------------
__device__ __forceinline__ void tile_map(int p, int& ti, int& tj) {
    ti = 0;
    while (p >= NT - ti) { p -= NT - ti; ++ti; }
    tj = ti + p;
}

// ------------------------------------------------------------------
// Phase 1: 128x128 upper tiles of A = |cov * r_i * r_j|.
// 256 threads, 8x8 register tile per thread, BK=16.
// Writes only the straight tile + deterministic row/col partial sums.
__global__ void __launch_bounds__(256, 2) k_corr() {
    __shared__ float sa[16][128];
    __shared__ float sb[16][128];
    __shared__ float rrow[128], rcol[128];
    __shared__ float rs[128];

    int b = blockIdx.y;
    int ti, tj;
    tile_map(blockIdx.x, ti, tj);
    int bRow = ti * 128, bCol = tj * 128;

    const float* Xb = g_Xc + (size_t)b * Nn * Dd;
    int t = threadIdx.x;
    int tx = t & 15, ty = t >> 4;

    if (t < 128) rrow[t] = g_r[b * Nn + bRow + t];
    else         rcol[t - 128] = g_r[b * Nn + bCol + (t - 128)];

    float acc[8][8];
#pragma unroll
    for (int i = 0; i < 8; ++i)
#pragma unroll
        for (int j = 0; j < 8; ++j) acc[i][j] = 0.f;

    int mload = t >> 2;
    int kq = (t & 3) << 2;

    for (int kc = 0; kc < 128; kc += 16) {
#pragma unroll
        for (int pp = 0; pp < 2; ++pp) {
            int m = mload + pp * 64;
            float4 va = *(const float4*)(Xb + (size_t)(bRow + m) * Dd + kc + kq);
            sa[kq + 0][m] = va.x; sa[kq + 1][m] = va.y;
            sa[kq + 2][m] = va.z; sa[kq + 3][m] = va.w;
            float4 vb = *(const float4*)(Xb + (size_t)(bCol + m) * Dd + kc + kq);
            sb[kq + 0][m] = vb.x; sb[kq + 1][m] = vb.y;
            sb[kq + 2][m] = vb.z; sb[kq + 3][m] = vb.w;
        }
        __syncthreads();
#pragma unroll
        for (int k = 0; k < 16; ++k) {
            float af[8], bf[8];
            *(float4*)&af[0] = *(const float4*)&sa[k][ty * 4];
            *(float4*)&af[4] = *(const float4*)&sa[k][64 + ty * 4];
            *(float4*)&bf[0] = *(const float4*)&sb[k][tx * 4];
            *(float4*)&bf[4] = *(const float4*)&sb[k][64 + tx * 4];
#pragma unroll
            for (int i = 0; i < 8; ++i)
#pragma unroll
                for (int j = 0; j < 8; ++j)
                    acc[i][j] += af[i] * bf[j];
        }
        __syncthreads();
    }

    // epilogue: scale + abs in place
    float rr_[8], rc_[8];
#pragma unroll
    for (int i = 0; i < 8; ++i) {
        int r = (i < 4) ? (ty * 4 + i) : (64 + ty * 4 + i - 4);
        rr_[i] = rrow[r];
    }
#pragma unroll
    for (int j = 0; j < 8; ++j) {
        int c = (j < 4) ? (tx * 4 + j) : (64 + tx * 4 + j - 4);
        rc_[j] = rcol[c];
    }
#pragma unroll
    for (int i = 0; i < 8; ++i)
#pragma unroll
        for (int j = 0; j < 8; ++j)
            acc[i][j] = fabsf(acc[i][j] * rr_[i] * rc_[j]);

    // straight tile write (float4, coalesced)
    float* Ab = g_A + (size_t)b * Nn * Nn;
#pragma unroll
    for (int i = 0; i < 8; ++i) {
        int r = (i < 4) ? (ty * 4 + i) : (64 + ty * 4 + i - 4);
        float4 w0 = make_float4(acc[i][0], acc[i][1], acc[i][2], acc[i][3]);
        float4 w1 = make_float4(acc[i][4], acc[i][5], acc[i][6], acc[i][7]);
        *(float4*)(Ab + (size_t)(bRow + r) * Nn + bCol + tx * 4)      = w0;
        *(float4*)(Ab + (size_t)(bRow + r) * Nn + bCol + 64 + tx * 4) = w1;
    }

    // row sums: per-thread sum of 8 cols, xor-shuffle over the 16 tx lanes
#pragma unroll
    for (int i = 0; i < 8; ++i) {
        float lr = 0.f;
#pragma unroll
        for (int j = 0; j < 8; ++j) lr += acc[i][j];
        for (int o = 8; o; o >>= 1) lr += __shfl_xor_sync(0xFFFFFFFFu, lr, o, 16);
        if (tx == 0) {
            int r = (i < 4) ? (ty * 4 + i) : (64 + ty * 4 + i - 4);
            rs[r] = lr;
        }
    }

    // col partial sums: reuse sa as [16][128] scratch (dead after mainloop)
#pragma unroll
    for (int j = 0; j < 8; ++j) {
        float lc = 0.f;
#pragma unroll
        for (int i = 0; i < 8; ++i) lc += acc[i][j];
        int c = (j < 4) ? (tx * 4 + j) : (64 + tx * 4 + j - 4);
        sa[ty][c] = lc;
    }
    __syncthreads();

    if (t < 128) {
        g_rowpart[b][tj][bRow + t] = rs[t];
        if (ti != tj) {
            float s = 0.f;
#pragma unroll
            for (int q = 0; q < 16; ++q) s += sa[q][t];
            g_rowpart[b][ti][bCol + t] = s;
        }
    }
}

// ------------------------------------------------------------------
// rowsum reduce (Kahan) ; d = rowsum^-0.5 ; w = d*y
__global__ void k_rowred() {
    int i = blockIdx.x * 256 + threadIdx.x;   // B*N = 32768
    int b = i >> 12, n = i & 4095;
    float s = 0.f, c = 0.f;
#pragma unroll
    for (int j = 0; j < NT; ++j) {
        float yk = g_rowpart[b][j][n] - c;
        float tt = s + yk;
        c = (tt - s) - yk;
        s = tt;
    }
    float dv = 1.0f / sqrtf(s);
    g_dvec[i] = dv;
    g_w[i] = dv * g_y[i];
}

// ------------------------------------------------------------------
// Phase 2: symmetric tile matvec. Each upper tile T(ti,tj) contributes
//   u[r] = T[r][:] . w[bCol..]  -> ypart[b][tj][bRow+r]
//   v[c] = T[:][c] . w[bRow..]  -> ypart[b][ti][bCol+c]   (ti != tj)
// grid (528, B), 256 threads. DRAM-streaming 270MB.
__global__ void __launch_bounds__(256) k_spmv() {
    __shared__ float sm[32][128];
    __shared__ float wr[128], wc[128];
    __shared__ float usum[128], vsum[128];

    int b = blockIdx.y;
    int ti, tj;
    tile_map(blockIdx.x, ti, tj);
    int bRow = ti * 128, bCol = tj * 128;
    int t = threadIdx.x;

    if (t < 128) { wr[t] = g_w[b * Nn + bRow + t]; vsum[t] = 0.f; }
    else         { wc[t - 128] = g_w[b * Nn + bCol + (t - 128)]; }
    __syncthreads();

    const float* Ab = g_A + (size_t)b * Nn * Nn;

    for (int s = 0; s < 4; ++s) {
#pragma unroll
        for (int q = 0; q < 4; ++q) {
            int off = q * 1024 + t * 4;
            int row = off >> 7, col = off & 127;
            *(float4*)&sm[row][col] =
                *(const float4*)(Ab + (size_t)(bRow + s * 32 + row) * Nn + bCol + col);
        }
        __syncthreads();
        // u: 8 lanes per row, 16 elements each, xor-shuffle width 8
        {
            int rr = t >> 3, g = t & 7;
            float pu = 0.f;
#pragma unroll
            for (int q = 0; q < 16; ++q) pu += sm[rr][g * 16 + q] * wc[g * 16 + q];
            for (int o = 4; o; o >>= 1) pu += __shfl_xor_sync(0xFFFFFFFFu, pu, o, 8);
            if (g == 0) usum[s * 32 + rr] = pu;
        }
        // v: one thread per column, serial over 32 strip rows (deterministic)
        if (t < 128) {
            float pv = 0.f;
#pragma unroll
            for (int rr = 0; rr < 32; ++rr) pv += sm[rr][t] * wr[s * 32 + rr];
            vsum[t] += pv;
        }
        __syncthreads();
    }

    if (t < 128) {
        g_ypart[b][tj][bRow + t] = usum[t];
        if (ti != tj) g_ypart[b][ti][bCol + t] = vsum[t];
    }
}

// ------------------------------------------------------------------
// S = d * (sum of 32 matvec partials)  (Kahan)
__global__ void k_sred(float* __restrict__ out) {
    int i = blockIdx.x * 256 + threadIdx.x;   // 32768
    int b = i >> 12, n = i & 4095;
    float s = 0.f, c = 0.f;
#pragma unroll
    for (int j = 0; j < NT; ++j) {
        float yk = g_ypart[b][j][n] - c;
        float tt = s + yk;
        c = (tt - s) - yk;
        s = tt;
    }
    out[OFF_S + i] = g_dvec[i] * (s + c);
}

// ------------------------------------------------------------------
// top-K via bitonic sort: descending score, ascending index on ties.
__global__ void k_topk(const float* __restrict__ S) {
    __shared__ unsigned long long key[4096];
    int b = blockIdx.x;
    for (int i = threadIdx.x; i < 4096; i += 1024) {
        unsigned u  = __float_as_uint(S[OFF_S + b * Nn + i]);
        unsigned up = (u & 0x80000000u) ? ~u : (u | 0x80000000u);
        unsigned kd = ~up;
        key[i] = ((unsigned long long)kd << 32) | (unsigned)i;
    }
    __syncthreads();
    for (int size = 2; size <= 4096; size <<= 1) {
        for (int stride = size >> 1; stride; stride >>= 1) {
#pragma unroll
            for (int q = 0; q < 2; ++q) {
                int t  = threadIdx.x + q * 1024;
                int lo = 2 * t - (t & (stride - 1));
                int hi = lo + stride;
                bool asc = (lo & size) == 0;
                unsigned long long a = key[lo], c = key[hi];
                if ((a > c) == asc) { key[lo] = c; key[hi] = a; }
            }
            __syncthreads();
        }
    }
    if (threadIdx.x < Kk)
        g_idx[b * Kk + threadIdx.x] = (int)(key[threadIdx.x] & 0xFFFFFFFFu);
}

// ------------------------------------------------------------------
// gather F_c, parallel over (b, k-chunk). grid (16, 8), 128 threads.
__global__ void k_gather(const float* __restrict__ X, float* __restrict__ out) {
    int b = blockIdx.y, kc = blockIdx.x, d = threadIdx.x;
#pragma unroll
    for (int q = 0; q < 16; ++q) {
        int k = kc * 16 + q;
        int n = g_idx[b * Kk + k];
        out[OFF_FC + ((size_t)b * Kk + k) * Dd + d] = X[((size_t)b * Nn + n) * Dd + d];
    }
}

// means: grid B, 128 threads (= d); reads gathered F_c back from out
__global__ void k_means(const float* __restrict__ X, float* __restrict__ out) {
    int b = blockIdx.x, d = threadIdx.x;
    float s = 0.f;
#pragma unroll 4
    for (int k = 0; k < Kk; ++k) {
        int n = g_idx[b * Kk + k];
        s += X[((size_t)b * Nn + n) * Dd + d];
    }
    out[OFF_FCM  + b * Dd + d] = s * (1.f / (float)Kk);
    out[OFF_FNCM + b * Dd + d] = (g_colsum[b * Dd + d] - s) * (1.f / (float)(Nn - Kk));
}

// ------------------------------------------------------------------
extern "C" void kernel_launch(void* const* d_in, const int* in_sizes, int n_in,
                              void* d_out, int out_size) {
    const float* X = (const float*)d_in[0];   // [8,4096,128] f32
    const float* W = (const float*)d_in[1];   // [1,128] f32
    float* out = (float*)d_out;

    dim3 gmp(32, Bb);
    k_meanpart<<<gmp, 128>>>(X);
    k_meanred<<<4, 256>>>();

    k_vary<<<Bb * Nn, 128>>>(X, W);

    dim3 gc(NTILES, Bb);
    k_corr<<<gc, 256>>>();

    k_rowred<<<128, 256>>>();

    k_spmv<<<gc, 256>>>();

    k_sred<<<128, 256>>>(out);

    k_topk<<<Bb, 1024>>>(out);

    dim3 gg(16, Bb);
    k_gather<<<gg, 128>>>(X, out);
    k_means<<<Bb, 128>>>(X, out);
}